// round 7
// baseline (speedup 1.0000x reference)
#include <cuda_runtime.h>
#include <math.h>

// ============================================================================
// EquivariantDecoder — R6: phase kernels rebuilt for L1-resident weights.
//   - weights read UNduplicated via LDG (L1-hit) + mov.b64 broadcast-pack
//   - NT=256, TB=32 rows/CTA; dynamic smem sized/padded so L1D >= weight block
//   - scalar tile loader (2-way STS conflicts instead of 8-way)
// gate kernels / layer4 / prep unchanged from the passing R4 version.
// ============================================================================

typedef unsigned long long u64;

#define BROWS 16384
#define HD    1856

__device__ __forceinline__ u64 ffma2(u64 a, u64 b, u64 c) {
    u64 d;
    asm("fma.rn.f32x2 %0, %1, %2, %3;" : "=l"(d) : "l"(a), "l"(b), "l"(c));
    return d;
}
__device__ __forceinline__ u64 pk1(float w) {
    u64 r;
    asm("mov.b64 %0, {%1, %1};" : "=l"(r) : "f"(w));
    return r;
}
__device__ __forceinline__ u64 pk2(float a, float b) {
    u64 r;
    asm("mov.b64 %0, {%1, %2};" : "=l"(r) : "f"(a), "f"(b));
    return r;
}
__device__ __forceinline__ float2 upk(u64 v) {
    float2 r;
    asm("mov.b64 {%0, %1}, %2;" : "=f"(r.x), "=f"(r.y) : "l"(v));
    return r;
}
__device__ __forceinline__ float sigf(float x) { return 1.0f / (1.0f + __expf(-x)); }

// ---- static device buffers (no allocation allowed) -------------------------
__device__ __align__(16) float g_h1[(size_t)BROWS * HD];
__device__ __align__(16) float g_h2[(size_t)BROWS * HD];
__device__ __align__(16) float g_gates[(size_t)BROWS * 256];  // [row-pair][256 gates][2 lanes]
__device__ __align__(16) float g_w1d[212992];                 // duplicated weights (gate kernels)
__device__ __align__(16) float g_w2d[65536];
__device__ __align__(16) float g_w3d[65536];

__global__ void prep_kernel(const float* __restrict__ w1,
                            const float* __restrict__ w2,
                            const float* __restrict__ w3) {
    int k = blockIdx.x * 256 + threadIdx.x;
    if (k < 106496) { float v = w1[k]; g_w1d[2 * k] = v; g_w1d[2 * k + 1] = v; }
    if (k < 32768)  { float v = w2[k]; g_w2d[2 * k] = v; g_w2d[2 * k + 1] = v;
                      float u = w3[k]; g_w3d[2 * k] = u; g_w3d[2 * k + 1] = u; }
}

// ============================================================================
// gate_kernel — unchanged from passing R4 version.
// ============================================================================
template <int MI0>
__global__ __launch_bounds__(160) void gate_kernel(
    const float* __restrict__ xin, int in_dim,
    const float* __restrict__ wdA, const float* __restrict__ wdB,
    float* __restrict__ hout, float* __restrict__ gates, float sc)
{
    constexpr int STRIDE = 34;
    __shared__ __align__(16) float sxs[MI0 * STRIDE];
    u64* sx64 = (u64*)sxs;

    const int tid = threadIdx.x;
    const int oc = tid % 40;
    const int rg = tid / 40;
    const int row0 = blockIdx.x * 32;

    for (int r = 0; r < 32; r++) {
        const float4* s4 = (const float4*)(xin + (size_t)(row0 + r) * in_dim);
        for (int c4 = tid; c4 < MI0 / 4; c4 += 160) {
            float4 v = __ldg(s4 + c4);
            sxs[(4 * c4 + 0) * STRIDE + r] = v.x;
            sxs[(4 * c4 + 1) * STRIDE + r] = v.y;
            sxs[(4 * c4 + 2) * STRIDE + r] = v.z;
            sxs[(4 * c4 + 3) * STRIDE + r] = v.w;
        }
    }
    __syncthreads();

    u64 acc[8][4];
#pragma unroll
    for (int k = 0; k < 8; k++)
#pragma unroll
        for (int j = 0; j < 4; j++) acc[k][j] = 0ull;

    const bool is_silu = (oc < 8);
    if (is_silu) {
        const ulonglong2* wr = (const ulonglong2*)wdA + oc * 4;   // dup row = 32 ull2
#pragma unroll 2
        for (int i = 0; i < MI0; i++) {
            u64 w[8];
#pragma unroll
            for (int q = 0; q < 4; q++) {
                ulonglong2 t = __ldg(wr + i * 32 + q);
                w[2 * q] = t.x; w[2 * q + 1] = t.y;
            }
#pragma unroll
            for (int j = 0; j < 4; j++) {
                u64 xv = sx64[i * 17 + (rg * 4 + j)];
#pragma unroll
                for (int k = 0; k < 8; k++) acc[k][j] = ffma2(xv, w[k], acc[k][j]);
            }
        }
    } else {
        const ulonglong2* wr = (const ulonglong2*)wdB + (oc - 8) * 4;  // dup row = 128 ull2
#pragma unroll 2
        for (int i = 0; i < MI0; i++) {
            u64 w[8];
#pragma unroll
            for (int q = 0; q < 4; q++) {
                ulonglong2 t = __ldg(wr + i * 128 + q);
                w[2 * q] = t.x; w[2 * q + 1] = t.y;
            }
#pragma unroll
            for (int j = 0; j < 4; j++) {
                u64 xv = sx64[i * 17 + (rg * 4 + j)];
#pragma unroll
                for (int k = 0; k < 8; k++) acc[k][j] = ffma2(xv, w[k], acc[k][j]);
            }
        }
    }

    if (is_silu) {
        const int o0 = oc * 8;
#pragma unroll
        for (int j = 0; j < 4; j++) {
            int r0 = row0 + (rg * 4 + j) * 2;
            float e0[8], e1[8];
#pragma unroll
            for (int k = 0; k < 8; k++) {
                float2 a = upk(acc[k][j]);
                float z0 = a.x * sc, z1 = a.y * sc;
                e0[k] = z0 * sigf(z0);
                e1[k] = z1 * sigf(z1);
            }
            float4* d0 = (float4*)(hout + (size_t)r0 * HD + o0);
            float4* d1 = (float4*)(hout + (size_t)(r0 + 1) * HD + o0);
            d0[0] = make_float4(e0[0], e0[1], e0[2], e0[3]);
            d0[1] = make_float4(e0[4], e0[5], e0[6], e0[7]);
            d1[0] = make_float4(e1[0], e1[1], e1[2], e1[3]);
            d1[1] = make_float4(e1[4], e1[5], e1[6], e1[7]);
        }
    } else {
        const int o0 = (oc - 8) * 8;
#pragma unroll
        for (int j = 0; j < 4; j++) {
            size_t bp = (size_t)(row0 / 2 + rg * 4 + j);
            u64 o[8];
#pragma unroll
            for (int k = 0; k < 8; k++) {
                float2 a = upk(acc[k][j]);
                o[k] = pk2(sigf(a.x * sc), sigf(a.y * sc));
            }
            ulonglong2* gp = (ulonglong2*)gates + (bp * 256 + o0) / 2;
#pragma unroll
            for (int q = 0; q < 4; q++)
                gp[q] = make_ulonglong2(o[2 * q], o[2 * q + 1]);
        }
    }
}

// ============================================================================
// phase2_kernel<MI,NM,MO,TB>: y[b,o,m] = sc * g[b,o] * sum_i x[b,i,m] w[i,o]
//   NT = 8*TB threads: oc = tid&15 (16 out-groups), rp = tid>>4 (TB/2 row-pairs)
//   x tile in dynamic smem, layout [rp][i*NM+m] as u64 row-pairs, row len FEATS+1
//   weights UNdup from global (L1-resident), broadcast-packed at use
// ============================================================================
template <int MI, int NM, int MO, int TB>
__global__ __launch_bounds__(8 * TB) void phase2_kernel(
    const float* __restrict__ xin, int in_dim, int in_off,
    const float* __restrict__ w, const float* __restrict__ gates,
    int goff, float* __restrict__ hout, int hoff, float sc)
{
    constexpr int OPT = MO / 16;
    constexpr int RP = TB / 2;
    constexpr int NT = 16 * RP;
    constexpr int FEATS = MI * NM;
    constexpr int ROWU = FEATS + 1;      // odd -> bank-safe rp stride

    extern __shared__ __align__(16) u64 sx[];
    float* sxf = (float*)sx;

    const int tid = threadIdx.x;
    const int oc = tid & 15;
    const int rp = tid >> 4;
    const int row0 = blockIdx.x * TB;

    // scalar tile loader: dst stride 2 floats across lanes (2-way conflicts)
    for (int r = 0; r < TB; r++) {
        const float* src = xin + (size_t)(row0 + r) * in_dim + in_off;
        float* dst = sxf + (size_t)(r >> 1) * (2 * ROWU) + (r & 1);
        for (int f = tid; f < FEATS; f += NT)
            dst[2 * f] = __ldg(src + f);
    }
    __syncthreads();

    u64 acc[OPT][NM];
#pragma unroll
    for (int j = 0; j < OPT; j++)
#pragma unroll
        for (int m = 0; m < NM; m++) acc[j][m] = 0ull;

    const u64* xp = sx + (size_t)rp * ROWU;

    if (OPT == 4) {
        const float4* wv = (const float4*)w + oc;   // row stride = MO/4 = 16
#pragma unroll 2
        for (int i = 0; i < MI; i++) {
            float4 t = __ldg(wv + i * 16);
            u64 w0 = pk1(t.x), w1 = pk1(t.y), w2 = pk1(t.z), w3 = pk1(t.w);
#pragma unroll
            for (int m = 0; m < NM; m++) {
                u64 xv = xp[i * NM + m];
                acc[0][m] = ffma2(xv, w0, acc[0][m]);
                acc[1][m] = ffma2(xv, w1, acc[1][m]);
                acc[2][m] = ffma2(xv, w2, acc[2][m]);
                acc[3][m] = ffma2(xv, w3, acc[3][m]);
            }
        }
    } else {
        const float2* wv = (const float2*)w + oc;   // row stride = MO/2 = 16
#pragma unroll 2
        for (int i = 0; i < MI; i++) {
            float2 t = __ldg(wv + i * 16);
            u64 w0 = pk1(t.x), w1 = pk1(t.y);
#pragma unroll
            for (int m = 0; m < NM; m++) {
                u64 xv = xp[i * NM + m];
                acc[0][m] = ffma2(xv, w0, acc[0][m]);
                acc[1][m] = ffma2(xv, w1, acc[1][m]);
            }
        }
    }

    // gates for this thread's outputs (row-pair packed)
    u64 g[OPT];
    const u64* gp = (const u64*)gates + (size_t)(row0 / 2 + rp) * 256 + goff + oc * OPT;
#pragma unroll
    for (int j = 0; j < OPT; j++) g[j] = __ldg(gp + j);

    __syncthreads();   // done reading x; reuse smem as output stage

#pragma unroll
    for (int j = 0; j < OPT; j++) {
        float2 gg = upk(g[j]);
#pragma unroll
        for (int m = 0; m < NM; m++) {
            float2 a = upk(acc[j][m]);
            int col = (oc * OPT + j) * NM + m;
            sxf[(size_t)(2 * rp) * (MO * NM) + col]     = a.x * sc * gg.x;
            sxf[(size_t)(2 * rp + 1) * (MO * NM) + col] = a.y * sc * gg.y;
        }
    }
    __syncthreads();

    constexpr int OUTF = MO * NM / 4;
    for (int r = 0; r < TB; r++) {
        float4* d = (float4*)(hout + (size_t)(row0 + r) * HD + hoff);
        const float4* s = (const float4*)(sxf + (size_t)r * (MO * NM));
        for (int c = tid; c < OUTF; c += NT) d[c] = s[c];
    }
}

// ============================================================================
// layer4: final projection HID -> 49 per row (unchanged)
// ============================================================================
__global__ __launch_bounds__(256) void layer4_kernel(
    const float* __restrict__ h, const float* __restrict__ w4,
    float* __restrict__ out)
{
    const int warp = threadIdx.x >> 5;
    const int lane = threadIdx.x & 31;
    const int row  = blockIdx.x * 8 + warp;

    const float* hr = h + (size_t)row * HD;

    const int MI[7]   = {64, 64, 64, 32, 32, 32, 32};
    const int XOFF[7] = {0, 64, 256, 576, 800, 1088, 1440};
    const int WOFF[7] = {0, 64, 128, 192, 224, 256, 288};
    const int OOFF[7] = {0, 1, 4, 9, 16, 25, 36};

#pragma unroll
    for (int l = 0; l < 7; l++) {
        const int nm = 2 * l + 1;
        const int mi = MI[l];
        const float sc = rsqrtf((float)mi);
        for (int m = 0; m < nm; m++) {
            float s = 0.0f;
            for (int i = lane; i < mi; i += 32)
                s += hr[XOFF[l] + i * nm + m] * __ldg(w4 + WOFF[l] + i);
#pragma unroll
            for (int off = 16; off; off >>= 1)
                s += __shfl_xor_sync(0xFFFFFFFFu, s, off);
            if (lane == 0)
                out[(size_t)row * 49 + OOFF[l] + m] = s * sc;
        }
    }
}

// ---- launch ----------------------------------------------------------------
extern "C" void kernel_launch(void* const* d_in, const int* in_sizes, int n_in,
                              void* d_out, int out_size)
{
    const float* v  = (const float*)d_in[0];
    const float* w1 = (const float*)d_in[1];
    const float* w2 = (const float*)d_in[2];
    const float* w3 = (const float*)d_in[3];
    const float* w4 = (const float*)d_in[4];
    float* out = (float*)d_out;

    float *h1, *h2, *gt, *w1d, *w2d, *w3d;
    cudaGetSymbolAddress((void**)&h1,  g_h1);
    cudaGetSymbolAddress((void**)&h2,  g_h2);
    cudaGetSymbolAddress((void**)&gt,  g_gates);
    cudaGetSymbolAddress((void**)&w1d, g_w1d);
    cudaGetSymbolAddress((void**)&w2d, g_w2d);
    cudaGetSymbolAddress((void**)&w3d, g_w3d);

    const float s256 = 1.0f / sqrtf(256.0f);
    const float s64  = 1.0f / sqrtf(64.0f);
    const float s128 = 1.0f / sqrtf(128.0f);
    const float s32  = 1.0f / sqrtf(32.0f);

    // smem sizes (bytes): 128*(FEATS+1), padded where needed to pin CTAs/SM
    // so that L1D (= 228KB - smem carveout) still holds the weight block.
    const int SM_L1_1 = 59392;   // (128,3,64) FEATS=384 nat 49280 -> pad: 3 CTAs, L1D 54KB
    const int SM_L1_2 = 82048;   // (128,5,64) FEATS=640: 2 CTAs, L1D 64KB
    const int SM_L1_3 = 57472;   // (64,7,32)  FEATS=448: 3 CTAs, L1D 56KB
    const int SM_L1_4 = 81920;   // (64,9,32)  FEATS=576 nat 73856 -> pad: 2 CTAs, L1D 64KB
    const int SM_L1_5 = 90240;   // (64,11,32) FEATS=704: 2 CTAs, L1D 47KB
    const int SM_L1_6 = 106624;  // (64,13,32) FEATS=832: 2 CTAs, L1D 15KB (w=8KB)
    const int SM_H_1  = 24704;   // (64,3,64)  FEATS=192
    const int SM_H_2  = 41088;   // (64,5,64)  FEATS=320
    const int SM_H_3  = 28800;   // (32,7,32)  FEATS=224
    const int SM_H_4  = 36992;   // (32,9,32)  FEATS=288
    const int SM_H_5  = 48128;   // (32,11,32) FEATS=352 nat 45184 -> pad: 4 CTAs, L1D 40KB
    const int SM_H_6  = 53376;   // (32,13,32) FEATS=416: 4 CTAs, L1D 15KB (w=4KB)

    // opt-in to >48KB dynamic smem (idempotent; first call is outside capture)
#define SETSM(K, SZ) cudaFuncSetAttribute((K), cudaFuncAttributeMaxDynamicSharedMemorySize, (SZ))
    SETSM((phase2_kernel<128,  3, 64, 32>), SM_L1_1);
    SETSM((phase2_kernel<128,  5, 64, 32>), SM_L1_2);
    SETSM((phase2_kernel< 64,  7, 32, 32>), SM_L1_3);
    SETSM((phase2_kernel< 64,  9, 32, 32>), SM_L1_4);
    SETSM((phase2_kernel< 64, 11, 32, 32>), SM_L1_5);
    SETSM((phase2_kernel< 64, 13, 32, 32>), SM_L1_6);
    SETSM((phase2_kernel< 64,  3, 64, 32>), SM_H_1);
    SETSM((phase2_kernel< 64,  5, 64, 32>), SM_H_2);
    SETSM((phase2_kernel< 32,  7, 32, 32>), SM_H_3);
    SETSM((phase2_kernel< 32,  9, 32, 32>), SM_H_4);
    SETSM((phase2_kernel< 32, 11, 32, 32>), SM_H_5);
    SETSM((phase2_kernel< 32, 13, 32, 32>), SM_H_6);
#undef SETSM

    prep_kernel<<<416, 256>>>(w1, w2, w3);

    const int G32 = BROWS / 32;   // 512

    // ---- layer 1: v(3840) -> h1
    gate_kernel<256><<<G32, 160>>>(v, 3840, w1d, w1d + 16384 * 2, h1, gt, s256);
    phase2_kernel<128,  3, 64, 32><<<G32, 256, SM_L1_1>>>(v, 3840,  256, w1 +  81920, gt,   0, h1,   64, s128);
    phase2_kernel<128,  5, 64, 32><<<G32, 256, SM_L1_2>>>(v, 3840,  640, w1 +  90112, gt,  64, h1,  256, s128);
    phase2_kernel< 64,  7, 32, 32><<<G32, 256, SM_L1_3>>>(v, 3840, 1280, w1 +  98304, gt, 128, h1,  576, s64);
    phase2_kernel< 64,  9, 32, 32><<<G32, 256, SM_L1_4>>>(v, 3840, 1728, w1 + 100352, gt, 160, h1,  800, s64);
    phase2_kernel< 64, 11, 32, 32><<<G32, 256, SM_L1_5>>>(v, 3840, 2304, w1 + 102400, gt, 192, h1, 1088, s64);
    phase2_kernel< 64, 13, 32, 32><<<G32, 256, SM_L1_6>>>(v, 3840, 3008, w1 + 104448, gt, 224, h1, 1440, s64);

    // ---- layer 2: h1 -> h2
    gate_kernel<64><<<G32, 160>>>(h1, HD, w2d, w2d + 4096 * 2, h2, gt, s64);
    phase2_kernel<64,  3, 64, 32><<<G32, 256, SM_H_1>>>(h1, HD,   64, w2 + 20480, gt,   0, h2,   64, s64);
    phase2_kernel<64,  5, 64, 32><<<G32, 256, SM_H_2>>>(h1, HD,  256, w2 + 24576, gt,  64, h2,  256, s64);
    phase2_kernel<32,  7, 32, 32><<<G32, 256, SM_H_3>>>(h1, HD,  576, w2 + 28672, gt, 128, h2,  576, s32);
    phase2_kernel<32,  9, 32, 32><<<G32, 256, SM_H_4>>>(h1, HD,  800, w2 + 29696, gt, 160, h2,  800, s32);
    phase2_kernel<32, 11, 32, 32><<<G32, 256, SM_H_5>>>(h1, HD, 1088, w2 + 30720, gt, 192, h2, 1088, s32);
    phase2_kernel<32, 13, 32, 32><<<G32, 256, SM_H_6>>>(h1, HD, 1440, w2 + 31744, gt, 224, h2, 1440, s32);

    // ---- layer 3: h2 -> h1
    gate_kernel<64><<<G32, 160>>>(h2, HD, w3d, w3d + 4096 * 2, h1, gt, s64);
    phase2_kernel<64,  3, 64, 32><<<G32, 256, SM_H_1>>>(h2, HD,   64, w3 + 20480, gt,   0, h1,   64, s64);
    phase2_kernel<64,  5, 64, 32><<<G32, 256, SM_H_2>>>(h2, HD,  256, w3 + 24576, gt,  64, h1,  256, s64);
    phase2_kernel<32,  7, 32, 32><<<G32, 256, SM_H_3>>>(h2, HD,  576, w3 + 28672, gt, 128, h1,  576, s32);
    phase2_kernel<32,  9, 32, 32><<<G32, 256, SM_H_4>>>(h2, HD,  800, w3 + 29696, gt, 160, h1,  800, s32);
    phase2_kernel<32, 11, 32, 32><<<G32, 256, SM_H_5>>>(h2, HD, 1088, w3 + 30720, gt, 192, h1, 1088, s32);
    phase2_kernel<32, 13, 32, 32><<<G32, 256, SM_H_6>>>(h2, HD, 1440, w3 + 31744, gt, 224, h1, 1440, s32);

    // ---- layer 4
    layer4_kernel<<<BROWS / 8, 256>>>(h1, w4, out);
}

// round 8
// speedup vs baseline: 1.6419x; 1.6419x over previous
#include <cuda_runtime.h>
#include <math.h>

// ============================================================================
// EquivariantDecoder — R7: high-occupancy phase kernels.
//   phase3: TB=8 rows/CTA, NT=128 (32 out-cols x 4 row-pairs), duplicated
//   weights (no pack movs), small static smem (12-27KB) -> 6-8 CTAs/SM.
//   gate/prep/layer4 kernels: unchanged from the passing R4 version.
// ============================================================================

typedef unsigned long long u64;

#define BROWS 16384
#define HD    1856

__device__ __forceinline__ u64 ffma2(u64 a, u64 b, u64 c) {
    u64 d;
    asm("fma.rn.f32x2 %0, %1, %2, %3;" : "=l"(d) : "l"(a), "l"(b), "l"(c));
    return d;
}
__device__ __forceinline__ u64 pk2(float a, float b) {
    u64 r;
    asm("mov.b64 %0, {%1, %2};" : "=l"(r) : "f"(a), "f"(b));
    return r;
}
__device__ __forceinline__ float2 upk(u64 v) {
    float2 r;
    asm("mov.b64 {%0, %1}, %2;" : "=f"(r.x), "=f"(r.y) : "l"(v));
    return r;
}
__device__ __forceinline__ float sigf(float x) { return 1.0f / (1.0f + __expf(-x)); }

// ---- static device buffers (no allocation allowed) -------------------------
__device__ __align__(16) float g_h1[(size_t)BROWS * HD];
__device__ __align__(16) float g_h2[(size_t)BROWS * HD];
__device__ __align__(16) float g_gates[(size_t)BROWS * 256];  // [row-pair][256 gates][2 lanes]
__device__ __align__(16) float g_w1d[212992];                 // duplicated weights
__device__ __align__(16) float g_w2d[65536];
__device__ __align__(16) float g_w3d[65536];

__global__ void prep_kernel(const float* __restrict__ w1,
                            const float* __restrict__ w2,
                            const float* __restrict__ w3) {
    int k = blockIdx.x * 256 + threadIdx.x;
    if (k < 106496) { float v = w1[k]; g_w1d[2 * k] = v; g_w1d[2 * k + 1] = v; }
    if (k < 32768)  { float v = w2[k]; g_w2d[2 * k] = v; g_w2d[2 * k + 1] = v;
                      float u = w3[k]; g_w3d[2 * k] = u; g_w3d[2 * k + 1] = u; }
}

// ============================================================================
// gate_kernel — unchanged from passing R4 version.
// ============================================================================
template <int MI0>
__global__ __launch_bounds__(160) void gate_kernel(
    const float* __restrict__ xin, int in_dim,
    const float* __restrict__ wdA, const float* __restrict__ wdB,
    float* __restrict__ hout, float* __restrict__ gates, float sc)
{
    constexpr int STRIDE = 34;
    __shared__ __align__(16) float sxs[MI0 * STRIDE];
    u64* sx64 = (u64*)sxs;

    const int tid = threadIdx.x;
    const int oc = tid % 40;
    const int rg = tid / 40;
    const int row0 = blockIdx.x * 32;

    for (int r = 0; r < 32; r++) {
        const float4* s4 = (const float4*)(xin + (size_t)(row0 + r) * in_dim);
        for (int c4 = tid; c4 < MI0 / 4; c4 += 160) {
            float4 v = __ldg(s4 + c4);
            sxs[(4 * c4 + 0) * STRIDE + r] = v.x;
            sxs[(4 * c4 + 1) * STRIDE + r] = v.y;
            sxs[(4 * c4 + 2) * STRIDE + r] = v.z;
            sxs[(4 * c4 + 3) * STRIDE + r] = v.w;
        }
    }
    __syncthreads();

    u64 acc[8][4];
#pragma unroll
    for (int k = 0; k < 8; k++)
#pragma unroll
        for (int j = 0; j < 4; j++) acc[k][j] = 0ull;

    const bool is_silu = (oc < 8);
    if (is_silu) {
        const ulonglong2* wr = (const ulonglong2*)wdA + oc * 4;   // dup row = 32 ull2
#pragma unroll 2
        for (int i = 0; i < MI0; i++) {
            u64 w[8];
#pragma unroll
            for (int q = 0; q < 4; q++) {
                ulonglong2 t = __ldg(wr + i * 32 + q);
                w[2 * q] = t.x; w[2 * q + 1] = t.y;
            }
#pragma unroll
            for (int j = 0; j < 4; j++) {
                u64 xv = sx64[i * 17 + (rg * 4 + j)];
#pragma unroll
                for (int k = 0; k < 8; k++) acc[k][j] = ffma2(xv, w[k], acc[k][j]);
            }
        }
    } else {
        const ulonglong2* wr = (const ulonglong2*)wdB + (oc - 8) * 4;  // dup row = 128 ull2
#pragma unroll 2
        for (int i = 0; i < MI0; i++) {
            u64 w[8];
#pragma unroll
            for (int q = 0; q < 4; q++) {
                ulonglong2 t = __ldg(wr + i * 128 + q);
                w[2 * q] = t.x; w[2 * q + 1] = t.y;
            }
#pragma unroll
            for (int j = 0; j < 4; j++) {
                u64 xv = sx64[i * 17 + (rg * 4 + j)];
#pragma unroll
                for (int k = 0; k < 8; k++) acc[k][j] = ffma2(xv, w[k], acc[k][j]);
            }
        }
    }

    if (is_silu) {
        const int o0 = oc * 8;
#pragma unroll
        for (int j = 0; j < 4; j++) {
            int r0 = row0 + (rg * 4 + j) * 2;
            float e0[8], e1[8];
#pragma unroll
            for (int k = 0; k < 8; k++) {
                float2 a = upk(acc[k][j]);
                float z0 = a.x * sc, z1 = a.y * sc;
                e0[k] = z0 * sigf(z0);
                e1[k] = z1 * sigf(z1);
            }
            float4* d0 = (float4*)(hout + (size_t)r0 * HD + o0);
            float4* d1 = (float4*)(hout + (size_t)(r0 + 1) * HD + o0);
            d0[0] = make_float4(e0[0], e0[1], e0[2], e0[3]);
            d0[1] = make_float4(e0[4], e0[5], e0[6], e0[7]);
            d1[0] = make_float4(e1[0], e1[1], e1[2], e1[3]);
            d1[1] = make_float4(e1[4], e1[5], e1[6], e1[7]);
        }
    } else {
        const int o0 = (oc - 8) * 8;
#pragma unroll
        for (int j = 0; j < 4; j++) {
            size_t bp = (size_t)(row0 / 2 + rg * 4 + j);
            u64 o[8];
#pragma unroll
            for (int k = 0; k < 8; k++) {
                float2 a = upk(acc[k][j]);
                o[k] = pk2(sigf(a.x * sc), sigf(a.y * sc));
            }
            ulonglong2* gp = (ulonglong2*)gates + (bp * 256 + o0) / 2;
#pragma unroll
            for (int q = 0; q < 4; q++)
                gp[q] = make_ulonglong2(o[2 * q], o[2 * q + 1]);
        }
    }
}

// ============================================================================
// phase3_kernel<MI,NM,MO>: y[b,o,m] = sc * g[b,o] * sum_i x[b,i,m] w[i,o]
//   NT=128: oc = tid&31 (32 out-groups), rp = tid>>5 (4 row-pairs, TB=8 rows)
//   OPT = MO/32 outputs/thread. Weights DUPLICATED -> LDG gives packed u64
//   directly (zero pack movs). x tile in small static smem; LDS address is
//   warp-uniform -> pure broadcast.
// ============================================================================
template <int MI, int NM, int MO>
__global__ __launch_bounds__(128, 8) void phase3_kernel(
    const float* __restrict__ xin, int in_dim, int in_off,
    const float* __restrict__ wd, const float* __restrict__ gates,
    int goff, float* __restrict__ hout, int hoff, float sc)
{
    constexpr int OPT = MO / 32;          // 2 (MO=64) or 1 (MO=32)
    constexpr int FEATS = MI * NM;
    constexpr int ROWU = FEATS + 1;       // u64 stride per row-pair
    constexpr int OUTLEN = MO * NM;

    __shared__ __align__(16) u64 sx[4 * ROWU];
    float* sxf = (float*)sx;

    const int tid = threadIdx.x;
    const int oc = tid & 31;
    const int rp = tid >> 5;
    const int row0 = blockIdx.x * 8;

    // ---- load x tile: row-pairs packed into u64 lanes ----
    for (int r = 0; r < 8; r++) {
        const float4* src = (const float4*)(xin + (size_t)(row0 + r) * in_dim + in_off);
        float* dst = sxf + (r >> 1) * (2 * ROWU) + (r & 1);
        for (int c = tid; c < FEATS / 4; c += 128) {
            float4 v = __ldg(src + c);
            dst[8 * c + 0] = v.x;
            dst[8 * c + 2] = v.y;
            dst[8 * c + 4] = v.z;
            dst[8 * c + 6] = v.w;
        }
    }
    __syncthreads();

    u64 acc[OPT][NM];
#pragma unroll
    for (int j = 0; j < OPT; j++)
#pragma unroll
        for (int m = 0; m < NM; m++) acc[j][m] = 0ull;

    const u64* xp = sx + rp * ROWU;

    if (OPT == 2) {
        // dup row = 64 u64 = 32 ull2; thread oc takes ull2 #oc
        const ulonglong2* wr = (const ulonglong2*)wd + oc;
#pragma unroll 2
        for (int i = 0; i < MI; i++) {
            ulonglong2 t = __ldg(wr + i * 32);
#pragma unroll
            for (int m = 0; m < NM; m++) {
                u64 xv = xp[i * NM + m];
                acc[0][m] = ffma2(xv, t.x, acc[0][m]);
                acc[1][m] = ffma2(xv, t.y, acc[1][m]);
            }
        }
    } else {
        // dup row = 32 u64; thread oc takes u64 #oc
        const u64* wr = (const u64*)wd + oc;
#pragma unroll 2
        for (int i = 0; i < MI; i++) {
            u64 t = __ldg(wr + i * 32);
#pragma unroll
            for (int m = 0; m < NM; m++)
                acc[0][m] = ffma2(xp[i * NM + m], t, acc[0][m]);
        }
    }

    // gates (row-pair packed)
    u64 g[OPT];
    const u64* gp = (const u64*)gates + (size_t)(row0 / 2 + rp) * 256 + goff + oc * OPT;
#pragma unroll
    for (int j = 0; j < OPT; j++) g[j] = __ldg(gp + j);

    __syncthreads();   // done reading x; reuse smem as output stage

#pragma unroll
    for (int j = 0; j < OPT; j++) {
        float2 gg = upk(g[j]);
#pragma unroll
        for (int m = 0; m < NM; m++) {
            float2 a = upk(acc[j][m]);
            int col = (oc * OPT + j) * NM + m;
            sxf[(2 * rp) * OUTLEN + col]     = a.x * sc * gg.x;
            sxf[(2 * rp + 1) * OUTLEN + col] = a.y * sc * gg.y;
        }
    }
    __syncthreads();

    for (int r = 0; r < 8; r++) {
        float4* d = (float4*)(hout + (size_t)(row0 + r) * HD + hoff);
        const float4* s = (const float4*)(sxf + r * OUTLEN);
        for (int c = tid; c < OUTLEN / 4; c += 128) d[c] = s[c];
    }
}

// ============================================================================
// layer4: final projection HID -> 49 per row (unchanged)
// ============================================================================
__global__ __launch_bounds__(256) void layer4_kernel(
    const float* __restrict__ h, const float* __restrict__ w4,
    float* __restrict__ out)
{
    const int warp = threadIdx.x >> 5;
    const int lane = threadIdx.x & 31;
    const int row  = blockIdx.x * 8 + warp;

    const float* hr = h + (size_t)row * HD;

    const int MI[7]   = {64, 64, 64, 32, 32, 32, 32};
    const int XOFF[7] = {0, 64, 256, 576, 800, 1088, 1440};
    const int WOFF[7] = {0, 64, 128, 192, 224, 256, 288};
    const int OOFF[7] = {0, 1, 4, 9, 16, 25, 36};

#pragma unroll
    for (int l = 0; l < 7; l++) {
        const int nm = 2 * l + 1;
        const int mi = MI[l];
        const float sc = rsqrtf((float)mi);
        for (int m = 0; m < nm; m++) {
            float s = 0.0f;
            for (int i = lane; i < mi; i += 32)
                s += hr[XOFF[l] + i * nm + m] * __ldg(w4 + WOFF[l] + i);
#pragma unroll
            for (int off = 16; off; off >>= 1)
                s += __shfl_xor_sync(0xFFFFFFFFu, s, off);
            if (lane == 0)
                out[(size_t)row * 49 + OOFF[l] + m] = s * sc;
        }
    }
}

// ---- launch ----------------------------------------------------------------
extern "C" void kernel_launch(void* const* d_in, const int* in_sizes, int n_in,
                              void* d_out, int out_size)
{
    const float* v  = (const float*)d_in[0];
    const float* w1 = (const float*)d_in[1];
    const float* w2 = (const float*)d_in[2];
    const float* w3 = (const float*)d_in[3];
    const float* w4 = (const float*)d_in[4];
    float* out = (float*)d_out;

    float *h1, *h2, *gt, *w1d, *w2d, *w3d;
    cudaGetSymbolAddress((void**)&h1,  g_h1);
    cudaGetSymbolAddress((void**)&h2,  g_h2);
    cudaGetSymbolAddress((void**)&gt,  g_gates);
    cudaGetSymbolAddress((void**)&w1d, g_w1d);
    cudaGetSymbolAddress((void**)&w2d, g_w2d);
    cudaGetSymbolAddress((void**)&w3d, g_w3d);

    const float s256 = 1.0f / sqrtf(256.0f);
    const float s128 = 1.0f / sqrtf(128.0f);
    const float s64  = 1.0f / sqrtf(64.0f);
    const float s32  = 1.0f / sqrtf(32.0f);

    prep_kernel<<<416, 256>>>(w1, w2, w3);

    const int G32 = BROWS / 32;   // 512  (gate kernels)
    const int G8  = BROWS / 8;    // 2048 (phase kernels)

    // ---- layer 1: v(3840) -> h1   (dup weight offsets = 2x original)
    gate_kernel<256><<<G32, 160>>>(v, 3840, w1d, w1d + 16384 * 2, h1, gt, s256);
    phase3_kernel<128,  3, 64><<<G8, 128>>>(v, 3840,  256, w1d +  81920 * 2, gt,   0, h1,   64, s128);
    phase3_kernel<128,  5, 64><<<G8, 128>>>(v, 3840,  640, w1d +  90112 * 2, gt,  64, h1,  256, s128);
    phase3_kernel< 64,  7, 32><<<G8, 128>>>(v, 3840, 1280, w1d +  98304 * 2, gt, 128, h1,  576, s64);
    phase3_kernel< 64,  9, 32><<<G8, 128>>>(v, 3840, 1728, w1d + 100352 * 2, gt, 160, h1,  800, s64);
    phase3_kernel< 64, 11, 32><<<G8, 128>>>(v, 3840, 2304, w1d + 102400 * 2, gt, 192, h1, 1088, s64);
    phase3_kernel< 64, 13, 32><<<G8, 128>>>(v, 3840, 3008, w1d + 104448 * 2, gt, 224, h1, 1440, s64);

    // ---- layer 2: h1 -> h2
    gate_kernel<64><<<G32, 160>>>(h1, HD, w2d, w2d + 4096 * 2, h2, gt, s64);
    phase3_kernel<64,  3, 64><<<G8, 128>>>(h1, HD,   64, w2d + 20480 * 2, gt,   0, h2,   64, s64);
    phase3_kernel<64,  5, 64><<<G8, 128>>>(h1, HD,  256, w2d + 24576 * 2, gt,  64, h2,  256, s64);
    phase3_kernel<32,  7, 32><<<G8, 128>>>(h1, HD,  576, w2d + 28672 * 2, gt, 128, h2,  576, s32);
    phase3_kernel<32,  9, 32><<<G8, 128>>>(h1, HD,  800, w2d + 29696 * 2, gt, 160, h2,  800, s32);
    phase3_kernel<32, 11, 32><<<G8, 128>>>(h1, HD, 1088, w2d + 30720 * 2, gt, 192, h2, 1088, s32);
    phase3_kernel<32, 13, 32><<<G8, 128>>>(h1, HD, 1440, w2d + 31744 * 2, gt, 224, h2, 1440, s32);

    // ---- layer 3: h2 -> h1
    gate_kernel<64><<<G32, 160>>>(h2, HD, w3d, w3d + 4096 * 2, h1, gt, s64);
    phase3_kernel<64,  3, 64><<<G8, 128>>>(h2, HD,   64, w3d + 20480 * 2, gt,   0, h1,   64, s64);
    phase3_kernel<64,  5, 64><<<G8, 128>>>(h2, HD,  256, w3d + 24576 * 2, gt,  64, h1,  256, s64);
    phase3_kernel<32,  7, 32><<<G8, 128>>>(h2, HD,  576, w3d + 28672 * 2, gt, 128, h1,  576, s32);
    phase3_kernel<32,  9, 32><<<G8, 128>>>(h2, HD,  800, w3d + 29696 * 2, gt, 160, h1,  800, s32);
    phase3_kernel<32, 11, 32><<<G8, 128>>>(h2, HD, 1088, w3d + 30720 * 2, gt, 192, h1, 1088, s32);
    phase3_kernel<32, 13, 32><<<G8, 128>>>(h2, HD, 1440, w3d + 31744 * 2, gt, 224, h1, 1440, s32);

    // ---- layer 4
    layer4_kernel<<<BROWS / 8, 256>>>(h1, w4, out);
}